// round 2
// baseline (speedup 1.0000x reference)
#include <cuda_runtime.h>

#define BB 16
#define CC 512
#define NN 2048
#define MAXH 70
#define MAXW 40
#define HW (MAXH * MAXW)          // 2800
#define HW4 (HW / 4)              // 700
#define CH_PER_BLK 16
#define BIGV 1000000

struct Params { int min_y, min_x, sy, sx, trans; };

__device__ Params g_params[BB];
__device__ int g_map[BB * HW];

// ---------------------------------------------------------------------------
// Kernel 1: per-batch bbox reduction + shift params. One block per batch.
// ---------------------------------------------------------------------------
__global__ void compute_params_kernel(const int* __restrict__ ys,
                                      const int* __restrict__ xs) {
    const int b = blockIdx.x;
    const int* y = ys + b * NN;
    const int* x = xs + b * NN;

    int mny = BIGV, mxy = -BIGV, mnx = BIGV, mxx = -BIGV;
    for (int n = threadIdx.x; n < NN; n += blockDim.x) {
        int yv = y[n];
        if (yv > -1) {
            int xv = x[n];
            mny = min(mny, yv); mxy = max(mxy, yv);
            mnx = min(mnx, xv); mxx = max(mxx, xv);
        }
    }
    #pragma unroll
    for (int o = 16; o > 0; o >>= 1) {
        mny = min(mny, __shfl_xor_sync(0xffffffffu, mny, o));
        mxy = max(mxy, __shfl_xor_sync(0xffffffffu, mxy, o));
        mnx = min(mnx, __shfl_xor_sync(0xffffffffu, mnx, o));
        mxx = max(mxx, __shfl_xor_sync(0xffffffffu, mxx, o));
    }
    __shared__ int s_mny[8], s_mxy[8], s_mnx[8], s_mxx[8];
    const int wid = threadIdx.x >> 5;
    const int lid = threadIdx.x & 31;
    if (lid == 0) { s_mny[wid] = mny; s_mxy[wid] = mxy; s_mnx[wid] = mnx; s_mxx[wid] = mxx; }
    __syncthreads();
    if (wid == 0) {
        int nw = blockDim.x >> 5;
        mny = (lid < nw) ? s_mny[lid] : BIGV;
        mxy = (lid < nw) ? s_mxy[lid] : -BIGV;
        mnx = (lid < nw) ? s_mnx[lid] : BIGV;
        mxx = (lid < nw) ? s_mxx[lid] : -BIGV;
        #pragma unroll
        for (int o = 4; o > 0; o >>= 1) {
            mny = min(mny, __shfl_xor_sync(0xffffffffu, mny, o));
            mxy = max(mxy, __shfl_xor_sync(0xffffffffu, mxy, o));
            mnx = min(mnx, __shfl_xor_sync(0xffffffffu, mnx, o));
            mxx = max(mxx, __shfl_xor_sync(0xffffffffu, mxx, o));
        }
        if (lid == 0) {
            int h = mxy - mny + 1;
            int w = mxx - mnx + 1;
            int trans = (w > h) ? 1 : 0;
            int H2 = trans ? w : h;
            int W2 = trans ? h : w;
            int hd = H2 - MAXH;
            int wd = W2 - MAXW;
            // numerators positive in both branches -> C int div == Python floor div
            int sy = (hd > 0) ? -((hd + 1) / 2) : ((1 - hd) / 2);
            int sx = (wd > 0) ? -((wd + 1) / 2) : ((1 - wd) / 2);
            Params p; p.min_y = mny; p.min_x = mnx; p.sy = sy; p.sx = sx; p.trans = trans;
            g_params[b] = p;
        }
    }
}

// ---------------------------------------------------------------------------
// Kernel 2: init pixel->point map to -1
// ---------------------------------------------------------------------------
__global__ void init_map_kernel() {
    int i = blockIdx.x * blockDim.x + threadIdx.x;
    if (i < BB * HW) g_map[i] = -1;
}

// ---------------------------------------------------------------------------
// Kernel 3: scatter point indices into the map.
// JAX/NumPy semantics: negative indices in [-dim, 0) WRAP; others dropped.
// Collisions resolved last-write-wins by point order -> atomicMax on n.
// ---------------------------------------------------------------------------
__global__ void build_map_kernel(const int* __restrict__ ys,
                                 const int* __restrict__ xs) {
    const int b = blockIdx.y;
    const int n = blockIdx.x * blockDim.x + threadIdx.x;
    if (n >= NN) return;
    int yv = ys[b * NN + n];
    if (yv <= -1) return;                 // invalid point
    int xv = xs[b * NN + n];
    Params p = g_params[b];
    int ry = yv - p.min_y;
    int rx = xv - p.min_x;
    int yy = p.trans ? rx : ry;
    int xx = p.trans ? ry : rx;
    int oy = yy + p.sy;
    int ox = xx + p.sx;
    if (oy < 0) oy += MAXH;               // NumPy-style wrap
    if (ox < 0) ox += MAXW;
    if (oy >= 0 && oy < MAXH && ox >= 0 && ox < MAXW)
        atomicMax(&g_map[b * HW + oy * MAXW + ox], n);
}

// ---------------------------------------------------------------------------
// Kernel 4: gather. One block per (batch, 16-channel chunk).
// Map staged in shared memory; float4 coalesced writes.
// ---------------------------------------------------------------------------
__global__ void __launch_bounds__(256)
gather_kernel(const float* __restrict__ features,
              const float* __restrict__ backend,
              float* __restrict__ out) {
    __shared__ int s_map[HW];
    const int b = blockIdx.y;
    const int c0 = blockIdx.x * CH_PER_BLK;

    // stage per-batch pixel->point map
    const int* gmap = g_map + b * HW;
    for (int i = threadIdx.x; i < HW; i += blockDim.x)
        s_map[i] = gmap[i];
    __syncthreads();

    #pragma unroll 1
    for (int cc = 0; cc < CH_PER_BLK; cc++) {
        const int c = c0 + cc;
        const float* frow = features + ((size_t)b * CC + c) * NN;
        float* orow = out + ((size_t)b * CC + c) * HW;
        const float back = __ldg(&backend[c]);
        for (int q = threadIdx.x; q < HW4; q += blockDim.x) {
            int p = q * 4;
            int i0 = s_map[p + 0];
            int i1 = s_map[p + 1];
            int i2 = s_map[p + 2];
            int i3 = s_map[p + 3];
            float4 v;
            v.x = (i0 >= 0) ? __ldg(&frow[i0]) : back;
            v.y = (i1 >= 0) ? __ldg(&frow[i1]) : back;
            v.z = (i2 >= 0) ? __ldg(&frow[i2]) : back;
            v.w = (i3 >= 0) ? __ldg(&frow[i3]) : back;
            *reinterpret_cast<float4*>(orow + p) = v;
        }
    }
}

extern "C" void kernel_launch(void* const* d_in, const int* in_sizes, int n_in,
                              void* d_out, int out_size) {
    // size-robust binding: features=16777216, backend=512, ys/xs=32768 (in order)
    const float* features = nullptr;
    const float* backend  = nullptr;
    const int*   ys       = nullptr;
    const int*   xs       = nullptr;
    for (int i = 0; i < n_in; i++) {
        if (in_sizes[i] == BB * CC * NN)      features = (const float*)d_in[i];
        else if (in_sizes[i] == CC)           backend  = (const float*)d_in[i];
        else if (in_sizes[i] == BB * NN) {
            if (!ys) ys = (const int*)d_in[i];
            else     xs = (const int*)d_in[i];
        }
    }
    float* out = (float*)d_out;  // [B, C, MAXH, MAXW]

    compute_params_kernel<<<BB, 256>>>(ys, xs);
    init_map_kernel<<<(BB * HW + 255) / 256, 256>>>();
    {
        dim3 grid((NN + 255) / 256, BB);
        build_map_kernel<<<grid, 256>>>(ys, xs);
    }
    {
        dim3 grid(CC / CH_PER_BLK, BB);   // 32 x 16 = 512 blocks
        gather_kernel<<<grid, 256>>>(features, backend, out);
    }
}

// round 3
// speedup vs baseline: 1.1331x; 1.1331x over previous
#include <cuda_runtime.h>

#define BB 16
#define CC 512
#define NN 2048
#define MAXH 70
#define MAXW 40
#define HW 2800           // MAXH*MAXW
#define HW4 700           // HW/4
#define CH 8              // channels per block
#define NTHR 256
#define PTS_PER_THR 8     // NN / NTHR
#define BIGV 1000000

// Single fused kernel: every block independently computes the per-batch
// params + pixel->point map in shared memory (cheap, ~2K cycles), then
// gathers CH channels with 32 independent loads in flight per thread.
__global__ void __launch_bounds__(NTHR)
fused_kernel(const float* __restrict__ features,   // [B, C, N]
             const float* __restrict__ backend,    // [C]
             const int*   __restrict__ ys,         // [B, N]
             const int*   __restrict__ xs,         // [B, N]
             float*       __restrict__ out)        // [B, C, MAXH, MAXW]
{
    __shared__ int s_map[HW];
    __shared__ int s_mny[8], s_mxy[8], s_mnx[8], s_mxx[8];
    __shared__ int s_par[5];   // min_y, min_x, sy, sx, trans

    const int b   = blockIdx.y;
    const int c0  = blockIdx.x * CH;
    const int tid = threadIdx.x;
    const int wid = tid >> 5;
    const int lid = tid & 31;

    // ---- 1. load coords (cached in regs for the scatter) + bbox reduce ----
    const int* y = ys + b * NN;
    const int* x = xs + b * NN;
    int ry[PTS_PER_THR], rx[PTS_PER_THR];
    int mny = BIGV, mxy = -BIGV, mnx = BIGV, mxx = -BIGV;
    #pragma unroll
    for (int k = 0; k < PTS_PER_THR; k++) {
        int n  = tid + k * NTHR;
        int yv = __ldg(&y[n]);
        int xv = __ldg(&x[n]);
        ry[k] = yv; rx[k] = xv;
        if (yv > -1) {
            mny = min(mny, yv); mxy = max(mxy, yv);
            mnx = min(mnx, xv); mxx = max(mxx, xv);
        }
    }
    #pragma unroll
    for (int o = 16; o > 0; o >>= 1) {
        mny = min(mny, __shfl_xor_sync(0xffffffffu, mny, o));
        mxy = max(mxy, __shfl_xor_sync(0xffffffffu, mxy, o));
        mnx = min(mnx, __shfl_xor_sync(0xffffffffu, mnx, o));
        mxx = max(mxx, __shfl_xor_sync(0xffffffffu, mxx, o));
    }
    if (lid == 0) { s_mny[wid] = mny; s_mxy[wid] = mxy; s_mnx[wid] = mnx; s_mxx[wid] = mxx; }

    // ---- 2. init map (overlaps with reduction; disjoint smem) ----
    #pragma unroll
    for (int i = tid; i < HW; i += NTHR) s_map[i] = -1;
    __syncthreads();

    // ---- 3. finalize params (warp 0) ----
    if (wid == 0) {
        mny = (lid < 8) ? s_mny[lid] : BIGV;
        mxy = (lid < 8) ? s_mxy[lid] : -BIGV;
        mnx = (lid < 8) ? s_mnx[lid] : BIGV;
        mxx = (lid < 8) ? s_mxx[lid] : -BIGV;
        #pragma unroll
        for (int o = 4; o > 0; o >>= 1) {
            mny = min(mny, __shfl_xor_sync(0xffffffffu, mny, o));
            mxy = max(mxy, __shfl_xor_sync(0xffffffffu, mxy, o));
            mnx = min(mnx, __shfl_xor_sync(0xffffffffu, mnx, o));
            mxx = max(mxx, __shfl_xor_sync(0xffffffffu, mxx, o));
        }
        if (lid == 0) {
            int h = mxy - mny + 1;
            int w = mxx - mnx + 1;
            int trans = (w > h) ? 1 : 0;
            int H2 = trans ? w : h;
            int W2 = trans ? h : w;
            int hd = H2 - MAXH;
            int wd = W2 - MAXW;
            // numerators positive in both branches -> C div == floor div
            int sy = (hd > 0) ? -((hd + 1) / 2) : ((1 - hd) / 2);
            int sx = (wd > 0) ? -((wd + 1) / 2) : ((1 - wd) / 2);
            s_par[0] = mny; s_par[1] = mnx; s_par[2] = sy; s_par[3] = sx; s_par[4] = trans;
        }
    }
    __syncthreads();

    const int min_y = s_par[0], min_x = s_par[1];
    const int sy = s_par[2], sx = s_par[3], trans = s_par[4];

    // ---- 4. scatter into smem map (wrap negatives NumPy-style;
    //          last-write-wins by point order -> atomicMax) ----
    #pragma unroll
    for (int k = 0; k < PTS_PER_THR; k++) {
        int yv = ry[k];
        if (yv > -1) {
            int xv = rx[k];
            int dy = yv - min_y;
            int dx = xv - min_x;
            int yy = trans ? dx : dy;
            int xx = trans ? dy : dx;
            int oy = yy + sy;
            int ox = xx + sx;
            if (oy < 0) oy += MAXH;
            if (ox < 0) ox += MAXW;
            if (oy >= 0 && oy < MAXH && ox >= 0 && ox < MAXW)
                atomicMax(&s_map[oy * MAXW + ox], tid + k * NTHR);
        }
    }
    __syncthreads();

    // ---- 5. gather: CH channels, float4 pixels, 32 loads in flight ----
    float back[CH];
    #pragma unroll
    for (int cc = 0; cc < CH; cc++) back[cc] = __ldg(&backend[c0 + cc]);

    const float* fbase = features + ((size_t)b * CC + c0) * NN;
    float*       obase = out      + ((size_t)b * CC + c0) * HW;

    for (int q = tid; q < HW4; q += NTHR) {
        int p  = q * 4;
        int i0 = s_map[p + 0];
        int i1 = s_map[p + 1];
        int i2 = s_map[p + 2];
        int i3 = s_map[p + 3];
        #pragma unroll
        for (int cc = 0; cc < CH; cc++) {
            const float* frow = fbase + cc * NN;
            float4 v;
            v.x = (i0 >= 0) ? __ldg(&frow[i0]) : back[cc];
            v.y = (i1 >= 0) ? __ldg(&frow[i1]) : back[cc];
            v.z = (i2 >= 0) ? __ldg(&frow[i2]) : back[cc];
            v.w = (i3 >= 0) ? __ldg(&frow[i3]) : back[cc];
            *reinterpret_cast<float4*>(obase + cc * HW + p) = v;
        }
    }
}

extern "C" void kernel_launch(void* const* d_in, const int* in_sizes, int n_in,
                              void* d_out, int out_size) {
    const float* features = nullptr;
    const float* backend  = nullptr;
    const int*   ys       = nullptr;
    const int*   xs       = nullptr;
    for (int i = 0; i < n_in; i++) {
        if (in_sizes[i] == BB * CC * NN)      features = (const float*)d_in[i];
        else if (in_sizes[i] == CC)           backend  = (const float*)d_in[i];
        else if (in_sizes[i] == BB * NN) {
            if (!ys) ys = (const int*)d_in[i];
            else     xs = (const int*)d_in[i];
        }
    }
    float* out = (float*)d_out;

    dim3 grid(CC / CH, BB);   // 64 x 16 = 1024 blocks
    fused_kernel<<<grid, NTHR>>>(features, backend, ys, xs, out);
}

// round 4
// speedup vs baseline: 1.2518x; 1.1048x over previous
#include <cuda_runtime.h>

#define BB 16
#define CC 512
#define NN 2048
#define MAXH 70
#define MAXW 40
#define HW 2800           // MAXH*MAXW
#define HW4 700           // HW/4
#define CH 8              // channels per block
#define NTHR 256
#define PTS_PER_THR 8     // NN / NTHR
#define BIGV 1000000
#define SMEM_BYTES (CH * NN * 4 + HW * 4)   // 65536 + 11200 = 76736

// Fused kernel. Per block: recompute per-batch params + pixel->point map in
// smem (cheap), stage CH feature rows into smem with coalesced float4 loads,
// then gather from smem (bank-conflict-cost ~3 vs ~25 L1tex wavefronts for
// the gathered-LDG version) and write coalesced float4 output.
__global__ void __launch_bounds__(NTHR)
fused_kernel(const float* __restrict__ features,   // [B, C, N]
             const float* __restrict__ backend,    // [C]
             const int*   __restrict__ ys,         // [B, N]
             const int*   __restrict__ xs,         // [B, N]
             float*       __restrict__ out)        // [B, C, MAXH, MAXW]
{
    extern __shared__ float s_dyn[];
    float* s_feat = s_dyn;                          // CH * NN floats
    int*   s_map  = (int*)(s_dyn + CH * NN);        // HW ints
    __shared__ int s_mny[8], s_mxy[8], s_mnx[8], s_mxx[8];
    __shared__ int s_par[5];

    const int b   = blockIdx.y;
    const int c0  = blockIdx.x * CH;
    const int tid = threadIdx.x;
    const int wid = tid >> 5;
    const int lid = tid & 31;

    // ---- 1. stage CH feature rows into smem (coalesced float4) ----
    // Issued first: long-latency DRAM streams overlap the prologue compute.
    const float4* fbase4 = (const float4*)(features + ((size_t)b * CC + c0) * NN);
    float4* s_feat4 = (float4*)s_feat;
    #pragma unroll
    for (int k = 0; k < (CH * NN / 4) / NTHR; k++)   // 16 iters
        s_feat4[tid + k * NTHR] = __ldg(&fbase4[tid + k * NTHR]);

    // ---- 2. load coords + bbox reduce ----
    const int* y = ys + b * NN;
    const int* x = xs + b * NN;
    int ry[PTS_PER_THR], rx[PTS_PER_THR];
    int mny = BIGV, mxy = -BIGV, mnx = BIGV, mxx = -BIGV;
    #pragma unroll
    for (int k = 0; k < PTS_PER_THR; k++) {
        int n  = tid + k * NTHR;
        int yv = __ldg(&y[n]);
        int xv = __ldg(&x[n]);
        ry[k] = yv; rx[k] = xv;
        if (yv > -1) {
            mny = min(mny, yv); mxy = max(mxy, yv);
            mnx = min(mnx, xv); mxx = max(mxx, xv);
        }
    }
    #pragma unroll
    for (int o = 16; o > 0; o >>= 1) {
        mny = min(mny, __shfl_xor_sync(0xffffffffu, mny, o));
        mxy = max(mxy, __shfl_xor_sync(0xffffffffu, mxy, o));
        mnx = min(mnx, __shfl_xor_sync(0xffffffffu, mnx, o));
        mxx = max(mxx, __shfl_xor_sync(0xffffffffu, mxx, o));
    }
    if (lid == 0) { s_mny[wid] = mny; s_mxy[wid] = mxy; s_mnx[wid] = mnx; s_mxx[wid] = mxx; }

    // ---- 3. init map ----
    #pragma unroll
    for (int i = tid; i < HW; i += NTHR) s_map[i] = -1;
    __syncthreads();

    // ---- 4. finalize params (warp 0) ----
    if (wid == 0) {
        mny = (lid < 8) ? s_mny[lid] : BIGV;
        mxy = (lid < 8) ? s_mxy[lid] : -BIGV;
        mnx = (lid < 8) ? s_mnx[lid] : BIGV;
        mxx = (lid < 8) ? s_mxx[lid] : -BIGV;
        #pragma unroll
        for (int o = 4; o > 0; o >>= 1) {
            mny = min(mny, __shfl_xor_sync(0xffffffffu, mny, o));
            mxy = max(mxy, __shfl_xor_sync(0xffffffffu, mxy, o));
            mnx = min(mnx, __shfl_xor_sync(0xffffffffu, mnx, o));
            mxx = max(mxx, __shfl_xor_sync(0xffffffffu, mxx, o));
        }
        if (lid == 0) {
            int h = mxy - mny + 1;
            int w = mxx - mnx + 1;
            int trans = (w > h) ? 1 : 0;
            int H2 = trans ? w : h;
            int W2 = trans ? h : w;
            int hd = H2 - MAXH;
            int wd = W2 - MAXW;
            // numerators positive in both branches -> C div == floor div
            int sy = (hd > 0) ? -((hd + 1) / 2) : ((1 - hd) / 2);
            int sx = (wd > 0) ? -((wd + 1) / 2) : ((1 - wd) / 2);
            s_par[0] = mny; s_par[1] = mnx; s_par[2] = sy; s_par[3] = sx; s_par[4] = trans;
        }
    }
    __syncthreads();

    const int min_y = s_par[0], min_x = s_par[1];
    const int sy = s_par[2], sx = s_par[3], trans = s_par[4];

    // ---- 5. scatter into smem map (wrap negatives NumPy-style;
    //          last-write-wins by point order -> atomicMax) ----
    #pragma unroll
    for (int k = 0; k < PTS_PER_THR; k++) {
        int yv = ry[k];
        if (yv > -1) {
            int xv = rx[k];
            int dy = yv - min_y;
            int dx = xv - min_x;
            int yy = trans ? dx : dy;
            int xx = trans ? dy : dx;
            int oy = yy + sy;
            int ox = xx + sx;
            if (oy < 0) oy += MAXH;
            if (ox < 0) ox += MAXW;
            if (oy >= 0 && oy < MAXH && ox >= 0 && ox < MAXW)
                atomicMax(&s_map[oy * MAXW + ox], tid + k * NTHR);
        }
    }
    __syncthreads();   // also fences the feature staging stores

    // ---- 6. gather from smem, coalesced float4 writes ----
    float back[CH];
    #pragma unroll
    for (int cc = 0; cc < CH; cc++) back[cc] = __ldg(&backend[c0 + cc]);

    float* obase = out + ((size_t)b * CC + c0) * HW;

    for (int q = tid; q < HW4; q += NTHR) {
        int p  = q * 4;
        int i0 = s_map[p + 0];
        int i1 = s_map[p + 1];
        int i2 = s_map[p + 2];
        int i3 = s_map[p + 3];
        #pragma unroll
        for (int cc = 0; cc < CH; cc++) {
            const float* srow = s_feat + cc * NN;
            float4 v;
            v.x = (i0 >= 0) ? srow[i0] : back[cc];
            v.y = (i1 >= 0) ? srow[i1] : back[cc];
            v.z = (i2 >= 0) ? srow[i2] : back[cc];
            v.w = (i3 >= 0) ? srow[i3] : back[cc];
            *reinterpret_cast<float4*>(obase + cc * HW + p) = v;
        }
    }
}

extern "C" void kernel_launch(void* const* d_in, const int* in_sizes, int n_in,
                              void* d_out, int out_size) {
    const float* features = nullptr;
    const float* backend  = nullptr;
    const int*   ys       = nullptr;
    const int*   xs       = nullptr;
    for (int i = 0; i < n_in; i++) {
        if (in_sizes[i] == BB * CC * NN)      features = (const float*)d_in[i];
        else if (in_sizes[i] == CC)           backend  = (const float*)d_in[i];
        else if (in_sizes[i] == BB * NN) {
            if (!ys) ys = (const int*)d_in[i];
            else     xs = (const int*)d_in[i];
        }
    }
    float* out = (float*)d_out;

    cudaFuncSetAttribute(fused_kernel,
                         cudaFuncAttributeMaxDynamicSharedMemorySize, SMEM_BYTES);
    dim3 grid(CC / CH, BB);   // 64 x 16 = 1024 blocks
    fused_kernel<<<grid, NTHR, SMEM_BYTES>>>(features, backend, ys, xs, out);
}

// round 5
// speedup vs baseline: 1.4151x; 1.1304x over previous
#include <cuda_runtime.h>

#define BB 16
#define CC 512
#define NN 2048
#define MAXH 70
#define MAXW 40
#define HW 2800           // MAXH*MAXW
#define HW4 700           // HW/4
#define CH 8              // channels per block
#define NTHR 512
#define NWARP (NTHR / 32)
#define PTS_PER_THR (NN / NTHR)   // 4
#define BIGV 1000000
#define SMEM_BYTES (CH * NN * 4 + HW * 4)   // 65536 + 11200 = 76736

__global__ void __launch_bounds__(NTHR)
fused_kernel(const float* __restrict__ features,   // [B, C, N]
             const float* __restrict__ backend,    // [C]
             const int*   __restrict__ ys,         // [B, N]
             const int*   __restrict__ xs,         // [B, N]
             float*       __restrict__ out)        // [B, C, MAXH, MAXW]
{
    extern __shared__ float s_dyn[];
    float* s_feat = s_dyn;                          // CH * NN floats
    int*   s_map  = (int*)(s_dyn + CH * NN);        // HW ints
    __shared__ int s_mny[NWARP], s_mxy[NWARP], s_mnx[NWARP], s_mxx[NWARP];
    __shared__ int s_par[5];

    const int b   = blockIdx.y;
    const int c0  = blockIdx.x * CH;
    const int tid = threadIdx.x;
    const int wid = tid >> 5;
    const int lid = tid & 31;

    // ---- 1. stage CH feature rows into smem (coalesced float4) ----
    const float4* fbase4 = (const float4*)(features + ((size_t)b * CC + c0) * NN);
    float4* s_feat4 = (float4*)s_feat;
    #pragma unroll
    for (int k = 0; k < (CH * NN / 4) / NTHR; k++)   // 8 iters
        s_feat4[tid + k * NTHR] = __ldg(&fbase4[tid + k * NTHR]);

    // ---- 2. load coords + bbox reduce ----
    const int* y = ys + b * NN;
    const int* x = xs + b * NN;
    int ry[PTS_PER_THR], rx[PTS_PER_THR];
    int mny = BIGV, mxy = -BIGV, mnx = BIGV, mxx = -BIGV;
    #pragma unroll
    for (int k = 0; k < PTS_PER_THR; k++) {
        int n  = tid + k * NTHR;
        int yv = __ldg(&y[n]);
        int xv = __ldg(&x[n]);
        ry[k] = yv; rx[k] = xv;
        if (yv > -1) {
            mny = min(mny, yv); mxy = max(mxy, yv);
            mnx = min(mnx, xv); mxx = max(mxx, xv);
        }
    }
    #pragma unroll
    for (int o = 16; o > 0; o >>= 1) {
        mny = min(mny, __shfl_xor_sync(0xffffffffu, mny, o));
        mxy = max(mxy, __shfl_xor_sync(0xffffffffu, mxy, o));
        mnx = min(mnx, __shfl_xor_sync(0xffffffffu, mnx, o));
        mxx = max(mxx, __shfl_xor_sync(0xffffffffu, mxx, o));
    }
    if (lid == 0) { s_mny[wid] = mny; s_mxy[wid] = mxy; s_mnx[wid] = mnx; s_mxx[wid] = mxx; }

    // ---- 3. init map ----
    for (int i = tid; i < HW; i += NTHR) s_map[i] = -1;
    __syncthreads();

    // ---- 4. finalize params (warp 0) ----
    if (wid == 0) {
        mny = (lid < NWARP) ? s_mny[lid] : BIGV;
        mxy = (lid < NWARP) ? s_mxy[lid] : -BIGV;
        mnx = (lid < NWARP) ? s_mnx[lid] : BIGV;
        mxx = (lid < NWARP) ? s_mxx[lid] : -BIGV;
        #pragma unroll
        for (int o = 8; o > 0; o >>= 1) {
            mny = min(mny, __shfl_xor_sync(0xffffffffu, mny, o));
            mxy = max(mxy, __shfl_xor_sync(0xffffffffu, mxy, o));
            mnx = min(mnx, __shfl_xor_sync(0xffffffffu, mnx, o));
            mxx = max(mxx, __shfl_xor_sync(0xffffffffu, mxx, o));
        }
        if (lid == 0) {
            int h = mxy - mny + 1;
            int w = mxx - mnx + 1;
            int trans = (w > h) ? 1 : 0;
            int H2 = trans ? w : h;
            int W2 = trans ? h : w;
            int hd = H2 - MAXH;
            int wd = W2 - MAXW;
            // numerators positive in both branches -> C div == floor div
            int sy = (hd > 0) ? -((hd + 1) / 2) : ((1 - hd) / 2);
            int sx = (wd > 0) ? -((wd + 1) / 2) : ((1 - wd) / 2);
            s_par[0] = mny; s_par[1] = mnx; s_par[2] = sy; s_par[3] = sx; s_par[4] = trans;
        }
    }
    __syncthreads();

    const int min_y = s_par[0], min_x = s_par[1];
    const int sy = s_par[2], sx = s_par[3], trans = s_par[4];

    // ---- 5. scatter into smem map (NumPy wrap for negatives;
    //          last-write-wins by point order -> atomicMax) ----
    #pragma unroll
    for (int k = 0; k < PTS_PER_THR; k++) {
        int yv = ry[k];
        if (yv > -1) {
            int xv = rx[k];
            int dy = yv - min_y;
            int dx = xv - min_x;
            int yy = trans ? dx : dy;
            int xx = trans ? dy : dx;
            int oy = yy + sy;
            int ox = xx + sx;
            if (oy < 0) oy += MAXH;
            if (ox < 0) ox += MAXW;
            if (oy >= 0 && oy < MAXH && ox >= 0 && ox < MAXW)
                atomicMax(&s_map[oy * MAXW + ox], tid + k * NTHR);
        }
    }
    __syncthreads();   // also fences the feature staging stores

    // ---- 6. gather from smem, coalesced float4 writes ----
    float back[CH];
    #pragma unroll
    for (int cc = 0; cc < CH; cc++) back[cc] = __ldg(&backend[c0 + cc]);

    float* obase = out + ((size_t)b * CC + c0) * HW;
    const int4* s_map4 = (const int4*)s_map;

    for (int q = tid; q < HW4; q += NTHR) {
        int4 im = s_map4[q];          // one LDS.128 for 4 pixel indices
        int p = q * 4;
        #pragma unroll
        for (int cc = 0; cc < CH; cc++) {
            const float* srow = s_feat + cc * NN;
            float4 v;
            v.x = (im.x >= 0) ? srow[im.x] : back[cc];
            v.y = (im.y >= 0) ? srow[im.y] : back[cc];
            v.z = (im.z >= 0) ? srow[im.z] : back[cc];
            v.w = (im.w >= 0) ? srow[im.w] : back[cc];
            *reinterpret_cast<float4*>(obase + cc * HW + p) = v;
        }
    }
}

extern "C" void kernel_launch(void* const* d_in, const int* in_sizes, int n_in,
                              void* d_out, int out_size) {
    const float* features = nullptr;
    const float* backend  = nullptr;
    const int*   ys       = nullptr;
    const int*   xs       = nullptr;
    for (int i = 0; i < n_in; i++) {
        if (in_sizes[i] == BB * CC * NN)      features = (const float*)d_in[i];
        else if (in_sizes[i] == CC)           backend  = (const float*)d_in[i];
        else if (in_sizes[i] == BB * NN) {
            if (!ys) ys = (const int*)d_in[i];
            else     xs = (const int*)d_in[i];
        }
    }
    float* out = (float*)d_out;

    cudaFuncSetAttribute(fused_kernel,
                         cudaFuncAttributeMaxDynamicSharedMemorySize, SMEM_BYTES);
    dim3 grid(CC / CH, BB);   // 64 x 16 = 1024 blocks
    fused_kernel<<<grid, NTHR, SMEM_BYTES>>>(features, backend, ys, xs, out);
}